// round 1
// baseline (speedup 1.0000x reference)
#include <cuda_runtime.h>
#include <math.h>

#define Bn 64
#define Tn 400
#define Hn 256
#define En 128
#define Vn 50000
#define Xn 500

// output layout (concatenated fp32, tuple order)
#define OFF_FINAL 0
#define OFF_HS   (Bn*(Vn+Xn))
#define OFF_CS   (OFF_HS + Bn*Hn)
#define OFF_CT   (OFF_CS + Bn*Hn)
#define OFF_ATTN (OFF_CT + Bn*2*Hn)
#define OFF_PGEN (OFF_ATTN + Bn*Tn)
#define OFF_COV  (OFF_PGEN + Bn)

// device scratch (no allocations allowed)
__device__ float g_x[Bn*En];
__device__ float g_gates[Bn*4*Hn];
__device__ float g_dec[Bn*2*Hn];
__device__ float g_scores[Bn*Tn];
__device__ float g_outhid[Bn*Hn];
__device__ float g_logits[Bn*Vn];
__device__ float g_stat[Bn*2];

__device__ __forceinline__ float warp_sum(float v){
    #pragma unroll
    for (int o = 16; o > 0; o >>= 1) v += __shfl_xor_sync(0xffffffffu, v, o);
    return v;
}
__device__ __forceinline__ float sigmoidf_(float x){ return 1.0f / (1.0f + expf(-x)); }

__device__ __forceinline__ unsigned long long pack2(float x, float y){
    unsigned long long r; asm("mov.b64 %0, {%1,%2};" : "=l"(r) : "f"(x), "f"(y)); return r;
}
__device__ __forceinline__ void unpack2(unsigned long long a, float &x, float &y){
    asm("mov.b64 {%0,%1}, %2;" : "=f"(x), "=f"(y) : "l"(a));
}
__device__ __forceinline__ unsigned long long fma2_(unsigned long long a, unsigned long long b, unsigned long long c){
    unsigned long long d; asm("fma.rn.f32x2 %0, %1, %2, %3;" : "=l"(d) : "l"(a), "l"(b), "l"(c)); return d;
}

// ---- misc: zero c_t output region + copy coverage ----
__global__ void k_misc(float* __restrict__ out, const float* __restrict__ coverage){
    int i = blockIdx.x * blockDim.x + threadIdx.x;
    if (i < Bn*2*Hn) out[OFF_CT + i] = 0.0f;
    if (i < Bn*Tn)   out[OFF_COV + i] = coverage[i];
}

// ---- x = cat([c_t_1, emb[y]]) @ Wxc^T + bxc : one warp per output ----
__global__ void k_build_x(const int* __restrict__ y_t_1, const float* __restrict__ c_t_1,
                          const float* __restrict__ embedding, const float* __restrict__ Wxc,
                          const float* __restrict__ bxc){
    int gw = (blockIdx.x * blockDim.x + threadIdx.x) >> 5;
    int lane = threadIdx.x & 31;
    if (gw >= Bn*En) return;
    int b = gw >> 7;          // /128
    int e = gw & 127;
    int y = y_t_1[b];
    float acc = 0.0f;
    for (int k = lane; k < 2*Hn + En; k += 32){
        float xv = (k < 2*Hn) ? c_t_1[b*2*Hn + k] : embedding[y*En + (k - 2*Hn)];
        acc += xv * Wxc[e*(2*Hn+En) + k];
    }
    acc = warp_sum(acc);
    if (lane == 0) g_x[b*En + e] = acc + bxc[e];
}

// ---- gates = x@W_ih^T + h0@W_hh^T + b_ih + b_hh : one warp per output ----
__global__ void k_gates(const float* __restrict__ h0, const float* __restrict__ W_ih,
                        const float* __restrict__ W_hh, const float* __restrict__ b_ih,
                        const float* __restrict__ b_hh){
    int gw = (blockIdx.x * blockDim.x + threadIdx.x) >> 5;
    int lane = threadIdx.x & 31;
    if (gw >= Bn*4*Hn) return;
    int b = gw >> 10;
    int j = gw & 1023;
    float acc = 0.0f;
    for (int k = lane; k < En; k += 32)
        acc += g_x[b*En + k] * W_ih[j*En + k];
    for (int k = lane; k < Hn; k += 32)
        acc += h0[b*Hn + k] * W_hh[j*Hn + k];
    acc = warp_sum(acc);
    if (lane == 0) g_gates[b*4*Hn + j] = acc + b_ih[j] + b_hh[j];
}

// ---- LSTM elementwise ----
__global__ void k_lstm(const float* __restrict__ c0, float* __restrict__ out){
    int i = blockIdx.x * blockDim.x + threadIdx.x;
    if (i >= Bn*Hn) return;
    int b = i / Hn, h = i % Hn;
    const float* gr = g_gates + b*4*Hn;
    float ig = sigmoidf_(gr[h]);
    float fg = sigmoidf_(gr[Hn + h]);
    float gg = tanhf(gr[2*Hn + h]);
    float og = sigmoidf_(gr[3*Hn + h]);
    float cs = fg * c0[i] + ig * gg;
    float hs = og * tanhf(cs);
    out[OFF_HS + i] = hs;
    out[OFF_CS + i] = cs;
}

// ---- dec_fea = s_t_hat @ Wdp^T + bdp : warp per output ----
__global__ void k_decfea(const float* __restrict__ out, const float* __restrict__ Wdp,
                         const float* __restrict__ bdp){
    int gw = (blockIdx.x * blockDim.x + threadIdx.x) >> 5;
    int lane = threadIdx.x & 31;
    if (gw >= Bn*2*Hn) return;
    int b = gw >> 9;
    int j = gw & 511;
    float acc = 0.0f;
    for (int k = lane; k < 2*Hn; k += 32){
        float sv = (k < Hn) ? out[OFF_HS + b*Hn + k] : out[OFF_CS + b*Hn + (k - Hn)];
        acc += sv * Wdp[j*2*Hn + k];
    }
    acc = warp_sum(acc);
    if (lane == 0) g_dec[b*2*Hn + j] = acc + bdp[j];
}

// ---- scores[b,t] = Wv . tanh(ef[b,t,:] + dec_fea[b,:]) : warp per (b,t) ----
__global__ void k_scores(const float* __restrict__ ef, const float* __restrict__ Wv){
    int gw = (blockIdx.x * blockDim.x + threadIdx.x) >> 5;
    int lane = threadIdx.x & 31;
    if (gw >= Bn*Tn) return;
    int b = gw / Tn;
    float acc = 0.0f;
    const float* efr = ef + (size_t)gw * (2*Hn);
    const float* dr = g_dec + b*2*Hn;
    for (int n = lane; n < 2*Hn; n += 32)
        acc += Wv[n] * tanhf(efr[n] + dr[n]);
    acc = warp_sum(acc);
    if (lane == 0) g_scores[gw] = acc;
}

// ---- softmax over T, mask, renorm, + stmt*mask ; write attn ----
__global__ void k_softmax_attn(const float* __restrict__ mask, const float* __restrict__ stmt,
                               float* __restrict__ out){
    int b = blockIdx.x;
    int t = threadIdx.x;  // 512 threads
    __shared__ float red[512];
    float s = (t < Tn) ? g_scores[b*Tn + t] : -1e30f;
    red[t] = s; __syncthreads();
    for (int k = 256; k > 0; k >>= 1){ if (t < k) red[t] = fmaxf(red[t], red[t+k]); __syncthreads(); }
    float mx = red[0]; __syncthreads();
    float e = (t < Tn) ? expf(s - mx) : 0.0f;
    red[t] = e; __syncthreads();
    for (int k = 256; k > 0; k >>= 1){ if (t < k) red[t] += red[t+k]; __syncthreads(); }
    float s1 = red[0]; __syncthreads();
    float mk = (t < Tn) ? mask[b*Tn + t] : 0.0f;
    float a = e / s1 * mk;
    red[t] = a; __syncthreads();
    for (int k = 256; k > 0; k >>= 1){ if (t < k) red[t] += red[t+k]; __syncthreads(); }
    float s2 = red[0];
    if (t < Tn){
        float av = a / s2 + stmt[b*Tn + t] * mk;
        out[OFF_ATTN + b*Tn + t] = av;
    }
}

// ---- c_t[b,n] = sum_t attn[b,t]*eo[b,t,n] ; split T over 8 blocks, atomic ----
__global__ void k_ct(const float* __restrict__ eo, float* __restrict__ out){
    int tc = blockIdx.x;       // 0..7
    int b  = blockIdx.y;       // 0..63
    int n  = threadIdx.x;      // 0..511
    __shared__ float at[64];
    if (n < 50) at[n] = out[OFF_ATTN + b*Tn + tc*50 + n];
    __syncthreads();
    float acc = 0.0f;
    const float* eor = eo + ((size_t)b*Tn + tc*50) * (2*Hn) + n;
    #pragma unroll 5
    for (int tt = 0; tt < 50; tt++)
        acc += at[tt] * eor[(size_t)tt * (2*Hn)];
    atomicAdd(&out[OFF_CT + b*2*Hn + n], acc);
}

// ---- p_gen = sigmoid([c_t, s_t_hat, x] . Wpg + bpg) : warp per b ----
__global__ void k_pgen(const float* __restrict__ Wpg, const float* __restrict__ bpg,
                       float* __restrict__ out){
    int gw = (blockIdx.x * blockDim.x + threadIdx.x) >> 5;
    int lane = threadIdx.x & 31;
    if (gw >= Bn) return;
    int b = gw;
    float acc = 0.0f;
    for (int k = lane; k < 4*Hn + En; k += 32){
        float v;
        if (k < 2*Hn)            v = out[OFF_CT + b*2*Hn + k];
        else if (k < 3*Hn)       v = out[OFF_HS + b*Hn + (k - 2*Hn)];
        else if (k < 4*Hn)       v = out[OFF_CS + b*Hn + (k - 3*Hn)];
        else                     v = g_x[b*En + (k - 4*Hn)];
        acc += v * Wpg[k];
    }
    acc = warp_sum(acc);
    if (lane == 0) out[OFF_PGEN + b] = sigmoidf_(acc + bpg[0]);
}

// ---- output = [h_s, c_t] @ Wo1^T + bo1 : warp per output ----
__global__ void k_outhid(const float* __restrict__ out, const float* __restrict__ Wo1,
                         const float* __restrict__ bo1){
    int gw = (blockIdx.x * blockDim.x + threadIdx.x) >> 5;
    int lane = threadIdx.x & 31;
    if (gw >= Bn*Hn) return;
    int b = gw >> 8;
    int j = gw & 255;
    float acc = 0.0f;
    for (int k = lane; k < 3*Hn; k += 32){
        float v = (k < Hn) ? out[OFF_HS + b*Hn + k] : out[OFF_CT + b*2*Hn + (k - Hn)];
        acc += v * Wo1[j*3*Hn + k];
    }
    acc = warp_sum(acc);
    if (lane == 0) g_outhid[b*Hn + j] = acc + bo1[j];
}

// ---- logits = outhid[64,256] @ Wo2^T[256,50000] + bo2 ; f32x2 tiled GEMM ----
__global__ void __launch_bounds__(256) k_logits(const float* __restrict__ W,
                                                const float* __restrict__ bias){
    __shared__ float As[32][65];    // [k][m]
    __shared__ float Bs[32][132];   // [k][n]
    int tid = threadIdx.x;
    int vbase = blockIdx.x * 128;
    int tx = tid & 31, ty = tid >> 5;
    int m0 = ty * 8, n0 = tx * 4;
    unsigned long long acc[8][2];
    #pragma unroll
    for (int i = 0; i < 8; i++){ acc[i][0] = 0ull; acc[i][1] = 0ull; }

    for (int kc = 0; kc < Hn; kc += 32){
        #pragma unroll
        for (int i = tid; i < 2048; i += 256){
            int m = i >> 5, kk = i & 31;
            As[kk][m] = g_outhid[m*Hn + kc + kk];
        }
        #pragma unroll
        for (int i4 = tid; i4 < 1024; i4 += 256){
            int row = i4 >> 3, k4 = i4 & 7;
            int v = vbase + row;
            float4 w = (v < Vn) ? *(const float4*)&W[(size_t)v*Hn + kc + k4*4]
                                : make_float4(0.f,0.f,0.f,0.f);
            Bs[k4*4+0][row] = w.x; Bs[k4*4+1][row] = w.y;
            Bs[k4*4+2][row] = w.z; Bs[k4*4+3][row] = w.w;
        }
        __syncthreads();
        #pragma unroll
        for (int kk = 0; kk < 32; kk++){
            float4 b4 = *(const float4*)&Bs[kk][n0];
            unsigned long long b01 = pack2(b4.x, b4.y);
            unsigned long long b23 = pack2(b4.z, b4.w);
            #pragma unroll
            for (int i = 0; i < 8; i++){
                float a = As[kk][m0 + i];
                unsigned long long a2 = pack2(a, a);
                acc[i][0] = fma2_(a2, b01, acc[i][0]);
                acc[i][1] = fma2_(a2, b23, acc[i][1]);
            }
        }
        __syncthreads();
    }
    #pragma unroll
    for (int i = 0; i < 8; i++){
        int m = m0 + i;
        float v0,v1,v2,v3;
        unpack2(acc[i][0], v0, v1);
        unpack2(acc[i][1], v2, v3);
        float vals[4] = {v0, v1, v2, v3};
        #pragma unroll
        for (int j = 0; j < 4; j++){
            int v = vbase + n0 + j;
            if (v < Vn) g_logits[(size_t)m*Vn + v] = vals[j] + bias[v];
        }
    }
}

// ---- per-row max + sumexp over V ----
__global__ void k_rowstat(){
    int b = blockIdx.x, tid = threadIdx.x;
    __shared__ float red[1024];
    const float* lr = g_logits + (size_t)b * Vn;
    float m = -1e30f;
    for (int v = tid; v < Vn; v += 1024) m = fmaxf(m, lr[v]);
    red[tid] = m; __syncthreads();
    for (int s = 512; s > 0; s >>= 1){ if (tid < s) red[tid] = fmaxf(red[tid], red[tid+s]); __syncthreads(); }
    m = red[0]; __syncthreads();
    float sum = 0.0f;
    for (int v = tid; v < Vn; v += 1024) sum += expf(lr[v] - m);
    red[tid] = sum; __syncthreads();
    for (int s = 512; s > 0; s >>= 1){ if (tid < s) red[tid] += red[tid+s]; __syncthreads(); }
    if (tid == 0){ g_stat[b*2] = m; g_stat[b*2+1] = red[0]; }
}

// ---- final_dist base: p_gen*softmax | extra_zeros ----
__global__ void k_final(const float* __restrict__ extraz, float* __restrict__ out){
    int i = blockIdx.x * blockDim.x + threadIdx.x;
    if (i >= Bn*(Vn+Xn)) return;
    int b = i / (Vn+Xn);
    int v = i - b*(Vn+Xn);
    float r;
    if (v < Vn){
        float pg = out[OFF_PGEN + b];
        r = pg * expf(g_logits[(size_t)b*Vn + v] - g_stat[b*2]) / g_stat[b*2+1];
    } else {
        r = extraz[b*Xn + (v - Vn)];
    }
    out[OFF_FINAL + i] = r;
}

// ---- scatter: final[b, idx] += (1-p_gen)*attn ----
__global__ void k_scatter(const int* __restrict__ ebev, float* __restrict__ out){
    int i = blockIdx.x * blockDim.x + threadIdx.x;
    if (i >= Bn*Tn) return;
    int b = i / Tn;
    int ix = ebev[i];
    float pg = out[OFF_PGEN + b];
    float add = (1.0f - pg) * out[OFF_ATTN + i];
    atomicAdd(&out[OFF_FINAL + (size_t)b*(Vn+Xn) + ix], add);
}

extern "C" void kernel_launch(void* const* d_in, const int* in_sizes, int n_in,
                              void* d_out, int out_size){
    const int*   y_t_1    = (const int*)  d_in[0];
    const float* h0       = (const float*)d_in[1];
    const float* c0       = (const float*)d_in[2];
    const float* eo       = (const float*)d_in[3];
    const float* ef       = (const float*)d_in[4];
    const float* stmt     = (const float*)d_in[5];
    const float* mask     = (const float*)d_in[6];
    const float* c_t_1    = (const float*)d_in[7];
    const float* extraz   = (const float*)d_in[8];
    const int*   ebev     = (const int*)  d_in[9];
    const float* coverage = (const float*)d_in[10];
    // parameters indexed from the end (robust to scalar 'step' presence)
    const float* embedding = (const float*)d_in[n_in-16];
    const float* Wxc  = (const float*)d_in[n_in-15];
    const float* bxc  = (const float*)d_in[n_in-14];
    const float* W_ih = (const float*)d_in[n_in-13];
    const float* W_hh = (const float*)d_in[n_in-12];
    const float* b_ih = (const float*)d_in[n_in-11];
    const float* b_hh = (const float*)d_in[n_in-10];
    const float* Wdp  = (const float*)d_in[n_in-9];
    const float* bdp  = (const float*)d_in[n_in-8];
    const float* Wv   = (const float*)d_in[n_in-7];
    const float* Wpg  = (const float*)d_in[n_in-6];
    const float* bpg  = (const float*)d_in[n_in-5];
    const float* Wo1  = (const float*)d_in[n_in-4];
    const float* bo1  = (const float*)d_in[n_in-3];
    const float* Wo2  = (const float*)d_in[n_in-2];
    const float* bo2  = (const float*)d_in[n_in-1];
    float* out = (float*)d_out;

    k_misc<<<(Bn*2*Hn + 255)/256, 256>>>(out, coverage);
    k_build_x<<<(Bn*En*32 + 255)/256, 256>>>(y_t_1, c_t_1, embedding, Wxc, bxc);
    k_gates<<<(Bn*4*Hn*32 + 255)/256, 256>>>(h0, W_ih, W_hh, b_ih, b_hh);
    k_lstm<<<(Bn*Hn + 255)/256, 256>>>(c0, out);
    k_decfea<<<(Bn*2*Hn*32 + 255)/256, 256>>>(out, Wdp, bdp);
    k_scores<<<(Bn*Tn*32 + 255)/256, 256>>>(ef, Wv);
    k_softmax_attn<<<Bn, 512>>>(mask, stmt, out);
    {
        dim3 g(8, Bn);
        k_ct<<<g, 512>>>(eo, out);
    }
    k_pgen<<<(Bn*32 + 255)/256, 256>>>(Wpg, bpg, out);
    k_outhid<<<(Bn*Hn*32 + 255)/256, 256>>>(out, Wo1, bo1);
    k_logits<<<(Vn + 127)/128, 256>>>(Wo2, bo2);
    k_rowstat<<<Bn, 1024>>>();
    k_final<<<(Bn*(Vn+Xn) + 255)/256, 256>>>(extraz, out);
    k_scatter<<<(Bn*Tn + 255)/256, 256>>>(ebev, out);
}